// round 9
// baseline (speedup 1.0000x reference)
#include <cuda_runtime.h>
#include <math.h>
#include <stdint.h>

#define NB    4
#define CDIM  256
#define HWDIM 128
#define NPIX  (HWDIM*HWDIM)    // 16384
#define HEADS 8
#define NPTS  4
#define HP    (HEADS*NPTS)     // 32
#define OWCOLS 96              // 64 offset cols + 32 attention-weight cols

// ---------------- scratch (device globals; no allocation allowed) ----------------
__device__ float g_v  [(size_t)NB * NPIX * CDIM];          // (b, n, c) c = h*32 + j
__device__ float g_ow [(size_t)2 * NB * NPIX * OWCOLS];    // (q, b, n, 96)
__device__ float g_cat[(size_t)NB * NPIX * 2 * CDIM];      // (b, n, 512)
__device__ float g_w96[2 * CDIM * OWCOLS];                 // (q, k, 96) = [Woff | Waw]
__device__ float g_b96[2 * OWCOLS];

// ---------------- packed f32x2 helpers ----------------
__device__ __forceinline__ uint64_t pack_dup_f32(float x) {
    uint64_t r; unsigned u = __float_as_uint(x);
    asm("mov.b64 %0, {%1, %1};" : "=l"(r) : "r"(u));
    return r;
}
__device__ __forceinline__ uint64_t ffma2(uint64_t a, uint64_t b, uint64_t c) {
    uint64_t d;
    asm("fma.rn.f32x2 %0, %1, %2, %3;" : "=l"(d) : "l"(a), "l"(b), "l"(c));
    return d;
}
__device__ __forceinline__ float2 unpack_f32x2(uint64_t v) {
    unsigned lo, hi;
    asm("mov.b64 {%0, %1}, %2;" : "=r"(lo), "=r"(hi) : "l"(v));
    return make_float2(__uint_as_float(lo), __uint_as_float(hi));
}

// ---------------- pack [Woff|Waw] into one 96-col weight per branch ----------------
__global__ void pack_w96_kernel(const float* __restrict__ Woff1, const float* __restrict__ Waw1,
                                const float* __restrict__ Woff2, const float* __restrict__ Waw2,
                                const float* __restrict__ boff1, const float* __restrict__ baw1,
                                const float* __restrict__ boff2, const float* __restrict__ baw2)
{
    int idx = blockIdx.x * blockDim.x + threadIdx.x;
    const int tot = 2 * CDIM * OWCOLS;
    if (idx < tot) {
        int q = idx / (CDIM * OWCOLS);
        int r = idx % (CDIM * OWCOLS);
        int k = r / OWCOLS;
        int j = r % OWCOLS;
        const float* Woff = q ? Woff2 : Woff1;
        const float* Waw  = q ? Waw2  : Waw1;
        g_w96[idx] = (j < 2 * HP) ? Woff[k * (2 * HP) + j] : Waw[k * HP + (j - 2 * HP)];
    }
    if (idx < 2 * OWCOLS) {
        int q = idx / OWCOLS;
        int j = idx % OWCOLS;
        const float* boff = q ? boff2 : boff1;
        const float* baw  = q ? baw2  : baw1;
        g_b96[idx] = (j < 2 * HP) ? boff[j] : baw[j - 2 * HP];
    }
}

// ---------------- fp32 SGEMM, 128xBNx8 tile, double-buffered smem, FFMA2 core ----------------
// BN = 128 (8 n/thread) or 96 (6 n/thread). Ncols must equal a multiple of BN covered by grid.y.
// A_STRIDED:  A(m,k) = A[k*Astride + m]   (x tensors: (B,C,N), K along C)
// !A_STRIDED: A(m,k) = A[m*Astride + k]   (row-major, Astride = lda = K)
// TRANS_OUT=false: C[m*ldc + n]           TRANS_OUT=true: C[n*ldc + m]
template<int BN, bool A_STRIDED, bool TRANS_OUT, bool HAS_BIAS>
__global__ __launch_bounds__(256, 2)
void sgemm_kernel(const float* __restrict__ A, const float* __restrict__ Bm,
                  const float* __restrict__ bias, float* __restrict__ C,
                  int Ncols, int K, int Astride,
                  size_t A_bstride, size_t C_bstride, int ldc)
{
    constexpr int BM = 128, BK = 8;
    constexpr int NPT   = BN / 16;        // n cols per thread: 8 or 6
    constexpr int NPAIR = NPT / 2;        // packed pairs: 4 or 3
    constexpr int BLD   = (BN * BK) / 256; // B elems loaded per thread per tile: 4 or 3

    __shared__ __align__(16) float As[2][BK][BM + 4];
    __shared__ __align__(16) float Bs[2][BK][BN];

    const int b = blockIdx.z;
    A += (size_t)b * A_bstride;
    C += (size_t)b * C_bstride;
    const int m0 = blockIdx.x * BM;
    const int n0 = blockIdx.y * BN;
    const int tid = threadIdx.x;

    int mbase, nbase;
    if (TRANS_OUT) { mbase = (tid & 15) * 4;   nbase = (tid >> 4) * NPT; }
    else           { nbase = (tid & 15) * NPT; mbase = (tid >> 4) * 4;   }

    uint64_t acc2[8][NPAIR];
#pragma unroll
    for (int i = 0; i < 8; i++)
#pragma unroll
        for (int jp = 0; jp < NPAIR; jp++) acc2[i][jp] = 0ull;   // packed {0.f, 0.f}

    float a_pref[4];
    float b_pref[BLD];

    // ---- prologue: load tile 0
    {
        if (A_STRIDED) {
#pragma unroll
            for (int i = 0; i < 4; i++) {
                int e = tid + i * 256;
                a_pref[i] = A[(size_t)(e >> 7) * Astride + (m0 + (e & 127))];
            }
        } else {
            int m = tid >> 1, kq = (tid & 1) * 4;
            float4 av = *(const float4*)(A + (size_t)(m0 + m) * Astride + kq);
            a_pref[0] = av.x; a_pref[1] = av.y; a_pref[2] = av.z; a_pref[3] = av.w;
        }
#pragma unroll
        for (int i = 0; i < BLD; i++) {
            int e = tid + i * 256;
            b_pref[i] = Bm[(size_t)(e / BN) * Ncols + n0 + (e % BN)];
        }
        if (A_STRIDED) {
#pragma unroll
            for (int i = 0; i < 4; i++) {
                int e = tid + i * 256;
                As[0][e >> 7][e & 127] = a_pref[i];
            }
        } else {
            int m = tid >> 1, kq = (tid & 1) * 4;
            As[0][kq + 0][m] = a_pref[0]; As[0][kq + 1][m] = a_pref[1];
            As[0][kq + 2][m] = a_pref[2]; As[0][kq + 3][m] = a_pref[3];
        }
#pragma unroll
        for (int i = 0; i < BLD; i++) {
            int e = tid + i * 256;
            Bs[0][e / BN][e % BN] = b_pref[i];
        }
    }
    __syncthreads();

    const int T = K / BK;
    for (int t = 0; t < T; t++) {
        const int cur = t & 1;
        const bool hasNext = (t + 1 < T);
        const int k1 = (t + 1) * BK;

        // prefetch next tile global -> regs (hidden under compute)
        if (hasNext) {
            if (A_STRIDED) {
#pragma unroll
                for (int i = 0; i < 4; i++) {
                    int e = tid + i * 256;
                    a_pref[i] = A[(size_t)(k1 + (e >> 7)) * Astride + (m0 + (e & 127))];
                }
            } else {
                int m = tid >> 1, kq = (tid & 1) * 4;
                float4 av = *(const float4*)(A + (size_t)(m0 + m) * Astride + (k1 + kq));
                a_pref[0] = av.x; a_pref[1] = av.y; a_pref[2] = av.z; a_pref[3] = av.w;
            }
#pragma unroll
            for (int i = 0; i < BLD; i++) {
                int e = tid + i * 256;
                b_pref[i] = Bm[(size_t)(k1 + e / BN) * Ncols + n0 + (e % BN)];
            }
        }

        // compute current tile
#pragma unroll
        for (int k = 0; k < BK; k++) {
            uint64_t b2[NPAIR];
            if (BN == 128) {
                ulonglong2 p0 = *(const ulonglong2*)&Bs[cur][k][nbase];
                ulonglong2 p1 = *(const ulonglong2*)&Bs[cur][k][nbase + 4];
                b2[0] = p0.x; b2[1] = p0.y; b2[2] = p1.x; b2[3] = p1.y;
            } else {
                b2[0] = *(const uint64_t*)&Bs[cur][k][nbase];
                b2[1] = *(const uint64_t*)&Bs[cur][k][nbase + 2];
                b2[2] = *(const uint64_t*)&Bs[cur][k][nbase + 4];
            }
            float4 a0 = *(const float4*)&As[cur][k][mbase];
            float4 a1 = *(const float4*)&As[cur][k][mbase + 64];
            float av[8] = {a0.x, a0.y, a0.z, a0.w, a1.x, a1.y, a1.z, a1.w};
#pragma unroll
            for (int i = 0; i < 8; i++) {
                uint64_t ad = pack_dup_f32(av[i]);
#pragma unroll
                for (int jp = 0; jp < NPAIR; jp++)
                    acc2[i][jp] = ffma2(ad, b2[jp], acc2[i][jp]);
            }
        }

        // store prefetched tile into the other stage
        if (hasNext) {
            const int nxt = cur ^ 1;
            if (A_STRIDED) {
#pragma unroll
                for (int i = 0; i < 4; i++) {
                    int e = tid + i * 256;
                    As[nxt][e >> 7][e & 127] = a_pref[i];
                }
            } else {
                int m = tid >> 1, kq = (tid & 1) * 4;
                As[nxt][kq + 0][m] = a_pref[0]; As[nxt][kq + 1][m] = a_pref[1];
                As[nxt][kq + 2][m] = a_pref[2]; As[nxt][kq + 3][m] = a_pref[3];
            }
#pragma unroll
            for (int i = 0; i < BLD; i++) {
                int e = tid + i * 256;
                Bs[nxt][e / BN][e % BN] = b_pref[i];
            }
            __syncthreads();
        }
    }

    // unpack packed accumulators to scalar 8 x NPT (contiguous n)
    float acc[8][NPT];
#pragma unroll
    for (int i = 0; i < 8; i++)
#pragma unroll
        for (int jp = 0; jp < NPAIR; jp++) {
            float2 u = unpack_f32x2(acc2[i][jp]);
            acc[i][2 * jp]     = u.x;
            acc[i][2 * jp + 1] = u.y;
        }

    if (!TRANS_OUT) {
        float bn_[NPT];
#pragma unroll
        for (int j = 0; j < NPT; j++)
            bn_[j] = HAS_BIAS ? bias[n0 + nbase + j] : 0.f;
#pragma unroll
        for (int mi = 0; mi < 8; mi++) {
            int m = m0 + mbase + (mi & 3) + ((mi & 4) ? 64 : 0);
            float* cr = C + (size_t)m * ldc + n0 + nbase;
            if (BN == 128) {
                *(float4*)(cr + 0) = make_float4(acc[mi][0] + bn_[0], acc[mi][1] + bn_[1],
                                                 acc[mi][2] + bn_[2], acc[mi][3] + bn_[3]);
                *(float4*)(cr + 4) = make_float4(acc[mi][4] + bn_[4], acc[mi][5] + bn_[5],
                                                 acc[mi][6] + bn_[6], acc[mi][7] + bn_[7]);
            } else {
                *(float2*)(cr + 0) = make_float2(acc[mi][0] + bn_[0], acc[mi][1] + bn_[1]);
                *(float2*)(cr + 2) = make_float2(acc[mi][2] + bn_[2], acc[mi][3] + bn_[3]);
                *(float2*)(cr + 4) = make_float2(acc[mi][4] + bn_[4], acc[mi][5] + bn_[5]);
            }
        }
    } else {
#pragma unroll
        for (int nj = 0; nj < NPT; nj++) {
            int n = n0 + nbase + nj;
            float bv = HAS_BIAS ? bias[n] : 0.f;
            float* cr = C + (size_t)n * ldc + m0;
            *(float4*)&cr[mbase]      = make_float4(acc[0][nj] + bv, acc[1][nj] + bv,
                                                    acc[2][nj] + bv, acc[3][nj] + bv);
            *(float4*)&cr[mbase + 64] = make_float4(acc[4][nj] + bv, acc[5][nj] + bv,
                                                    acc[6][nj] + bv, acc[7][nj] + bv);
        }
    }
}

// ---------------- fused softmax + bilinear sampling + weighted sum ----------------
// grid: (NPIX, NB, 2 branches), block: 256 (8 warps = 8 heads, 32 lanes = d)
__global__ __launch_bounds__(256) void sample_kernel()
{
    const int n = blockIdx.x;
    const int b = blockIdx.y;
    const int q = blockIdx.z;
    const int tid = threadIdx.x;
    const int h = tid >> 5;
    const int j = tid & 31;

    const float* __restrict__ owp =
        g_ow + ((size_t)q * NB * NPIX + (size_t)b * NPIX + n) * OWCOLS;

    // softmax over the 32 flattened (head, point) logits — each lane holds one
    float logit = owp[2 * HP + j];
    float mx = logit;
#pragma unroll
    for (int o = 16; o; o >>= 1) mx = fmaxf(mx, __shfl_xor_sync(0xffffffffu, mx, o));
    float ex = __expf(logit - mx);
    float sm = ex;
#pragma unroll
    for (int o = 16; o; o >>= 1) sm += __shfl_xor_sync(0xffffffffu, sm, o);
    float aw = ex / sm;

    const int px = n & (HWDIM - 1);
    const int py = n >> 7;
    // mirror reference arithmetic exactly to keep floor() decisions identical
    const float refx = ((float)px + 0.5f) / (float)HWDIM;
    const float refy = ((float)py + 0.5f) / (float)HWDIM;

    const float* __restrict__ vb = g_v + (size_t)b * NPIX * CDIM + h * 32 + j;
    const float2* __restrict__ offp = (const float2*)(owp + h * (2 * NPTS));
    float acc = 0.f;
#pragma unroll
    for (int p = 0; p < NPTS; p++) {
        float ax = __shfl_sync(0xffffffffu, aw, h * NPTS + p);
        float2 o2 = offp[p];
        float gx = 2.0f * (refx + o2.x) - 1.0f;
        float gy = 2.0f * (refy + o2.y) - 1.0f;
        float ix = ((gx + 1.0f) * (float)HWDIM - 1.0f) * 0.5f;
        float iy = ((gy + 1.0f) * (float)HWDIM - 1.0f) * 0.5f;
        float x0f = floorf(ix), y0f = floorf(iy);
        float wx1 = ix - x0f,   wy1 = iy - y0f;
        int x0 = (int)x0f, y0 = (int)y0f;
        float w00 = (1.f - wx1) * (1.f - wy1);
        float w10 = wx1 * (1.f - wy1);
        float w01 = (1.f - wx1) * wy1;
        float w11 = wx1 * wy1;
        float s = 0.f;
        if ((unsigned)x0 < HWDIM && (unsigned)y0 < HWDIM)
            s = fmaf(w00, vb[(size_t)(y0 * HWDIM + x0) * CDIM], s);
        if ((unsigned)(x0 + 1) < HWDIM && (unsigned)y0 < HWDIM)
            s = fmaf(w10, vb[(size_t)(y0 * HWDIM + x0 + 1) * CDIM], s);
        if ((unsigned)x0 < HWDIM && (unsigned)(y0 + 1) < HWDIM)
            s = fmaf(w01, vb[(size_t)((y0 + 1) * HWDIM + x0) * CDIM], s);
        if ((unsigned)(x0 + 1) < HWDIM && (unsigned)(y0 + 1) < HWDIM)
            s = fmaf(w11, vb[(size_t)((y0 + 1) * HWDIM + x0 + 1) * CDIM], s);
        acc = fmaf(ax, s, acc);
    }
    g_cat[((size_t)b * NPIX + n) * (2 * CDIM) + q * CDIM + h * 32 + j] = acc;
}

// ---------------- launch ----------------
extern "C" void kernel_launch(void* const* d_in, const int* in_sizes, int n_in,
                              void* d_out, int out_size)
{
    const float* x1    = (const float*)d_in[0];
    const float* x2    = (const float*)d_in[1];
    const float* x3    = (const float*)d_in[2];
    const float* Wv    = (const float*)d_in[3];
    const float* Woff1 = (const float*)d_in[4];
    const float* boff1 = (const float*)d_in[5];
    const float* Woff2 = (const float*)d_in[6];
    const float* boff2 = (const float*)d_in[7];
    const float* Waw1  = (const float*)d_in[8];
    const float* baw1  = (const float*)d_in[9];
    const float* Waw2  = (const float*)d_in[10];
    const float* baw2  = (const float*)d_in[11];
    const float* Wout  = (const float*)d_in[12];
    const float* bout  = (const float*)d_in[13];
    float* out = (float*)d_out;

    float *p_v, *p_ow, *p_cat, *p_w96, *p_b96;
    cudaGetSymbolAddress((void**)&p_v,   g_v);
    cudaGetSymbolAddress((void**)&p_ow,  g_ow);
    cudaGetSymbolAddress((void**)&p_cat, g_cat);
    cudaGetSymbolAddress((void**)&p_w96, g_w96);
    cudaGetSymbolAddress((void**)&p_b96, g_b96);

    // 1) pack branch weights into [Woff|Waw]
    pack_w96_kernel<<<(2 * CDIM * OWCOLS + 255) / 256, 256>>>(
        Woff1, Waw1, Woff2, Waw2, boff1, baw1, boff2, baw2);

    // 2) v = x3^T @ Wv   -> g_v (b, n, c)
    sgemm_kernel<128, true, false, false><<<dim3(NPIX / 128, CDIM / 128, NB), 256>>>(
        x3, Wv, nullptr, p_v,
        CDIM, CDIM, /*Astride=*/NPIX,
        (size_t)CDIM * NPIX, (size_t)NPIX * CDIM, /*ldc=*/CDIM);

    // 3) [off|aw] = x{1,2}^T @ W96 + b96 -> g_ow  (exact-fit BN=96 tiles)
    sgemm_kernel<96, true, false, true><<<dim3(NPIX / 128, 1, NB), 256>>>(
        x1, p_w96, p_b96, p_ow,
        OWCOLS, CDIM, NPIX,
        (size_t)CDIM * NPIX, (size_t)NPIX * OWCOLS, OWCOLS);
    sgemm_kernel<96, true, false, true><<<dim3(NPIX / 128, 1, NB), 256>>>(
        x2, p_w96 + CDIM * OWCOLS, p_b96 + OWCOLS, p_ow + (size_t)NB * NPIX * OWCOLS,
        OWCOLS, CDIM, NPIX,
        (size_t)CDIM * NPIX, (size_t)NPIX * OWCOLS, OWCOLS);

    // 4) softmax + bilinear sample + point-weighted sum -> g_cat (b, n, 512)
    sample_kernel<<<dim3(NPIX, NB, 2), 256>>>();

    // 5) out = cat @ Wout + bout, written transposed to (B, C, H, W)
    sgemm_kernel<128, false, true, true><<<dim3(NPIX / 128, CDIM / 128, NB), 256>>>(
        p_cat, Wout, bout, out,
        CDIM, 2 * CDIM, /*lda=*/2 * CDIM,
        (size_t)NPIX * 2 * CDIM, (size_t)CDIM * NPIX, /*ldc=*/NPIX);
}

// round 13
// speedup vs baseline: 1.3246x; 1.3246x over previous
#include <cuda_runtime.h>
#include <cuda_bf16.h>
#include <math.h>
#include <stdint.h>

#define NB    4
#define CDIM  256
#define HWDIM 128
#define NPIX  (HWDIM*HWDIM)    // 16384
#define HEADS 8
#define NPTS  4
#define HP    32
#define OWCOLS 96

// ---------------- scratch (device globals; no allocation allowed) ----------------
// split-bf16 A-operands, chunk-major: (b, chunk, pixel, 64); segs [hi|hi|lo]
__device__ __align__(128) __nv_bfloat16 g_x1S [(size_t)NB*12*NPIX*64];
__device__ __align__(128) __nv_bfloat16 g_x2S [(size_t)NB*12*NPIX*64];
__device__ __align__(128) __nv_bfloat16 g_x3S [(size_t)NB*12*NPIX*64];
__device__ __align__(128) __nv_bfloat16 g_catS[(size_t)NB*24*NPIX*64];
// transposed split weights: (n, k') row-major with k' = [hi | lo | hi]
__device__ __align__(128) __nv_bfloat16 g_WTv  [256*768];
__device__ __align__(128) __nv_bfloat16 g_WTow [2*96*768];
__device__ __align__(128) __nv_bfloat16 g_WTout[256*1536];
__device__ float g_v  [(size_t)NB*NPIX*CDIM];          // (b, pix, c)
__device__ float g_ow [(size_t)2*NB*NPIX*OWCOLS];      // (q, b, pix, 96)
__device__ float g_b96[2*OWCOLS];

// ---------------- bf16 warp MMA (baseline PTX, works on compute_103) ----------------
__device__ __forceinline__ void mma_bf16(float* d, const uint32_t* a, const uint32_t* b) {
    asm volatile(
        "mma.sync.aligned.m16n8k16.row.col.f32.bf16.bf16.f32 "
        "{%0,%1,%2,%3}, {%4,%5,%6,%7}, {%8,%9}, {%0,%1,%2,%3};"
        : "+f"(d[0]), "+f"(d[1]), "+f"(d[2]), "+f"(d[3])
        : "r"(a[0]), "r"(a[1]), "r"(a[2]), "r"(a[3]), "r"(b[0]), "r"(b[1]));
}

// ---------------- weight conversion: transpose + 3-segment split [hi|lo|hi] ----------------
__global__ void convert_w_kernel(const float* __restrict__ Wv,
                                 const float* __restrict__ Woff1, const float* __restrict__ Waw1,
                                 const float* __restrict__ Woff2, const float* __restrict__ Waw2,
                                 const float* __restrict__ boff1, const float* __restrict__ baw1,
                                 const float* __restrict__ boff2, const float* __restrict__ baw2,
                                 const float* __restrict__ Wout)
{
    int idx = blockIdx.x * blockDim.x + threadIdx.x;
    const int NV = 256*768, NOW = 2*96*768, NOUT = 256*1536;
    float v; __nv_bfloat16* dst; int seg;
    if (idx < NV) {
        int n = idx / 768, kp = idx % 768; seg = kp / 256; int k = kp % 256;
        v = Wv[k*256 + n]; dst = &g_WTv[idx];
    } else if (idx < NV + NOW) {
        int r = idx - NV; int q = r / (96*768); int rem = r % (96*768);
        int n = rem / 768, kp = rem % 768; seg = kp / 256; int k = kp % 256;
        const float* Woff = q ? Woff2 : Woff1;
        const float* Waw  = q ? Waw2  : Waw1;
        v = (n < 64) ? Woff[k*64 + n] : Waw[k*32 + (n - 64)];
        dst = &g_WTow[r];
    } else if (idx < NV + NOW + NOUT) {
        int r = idx - NV - NOW; int n = r / 1536, kp = r % 1536; seg = kp / 512; int k = kp % 512;
        v = Wout[k*256 + n]; dst = &g_WTout[r];
    } else if (idx < NV + NOW + NOUT + 2*OWCOLS) {
        int r = idx - NV - NOW - NOUT; int q = r / OWCOLS, j = r % OWCOLS;
        const float* boff = q ? boff2 : boff1;
        const float* baw  = q ? baw2  : baw1;
        g_b96[r] = (j < 64) ? boff[j] : baw[j - 64];
        return;
    } else return;
    __nv_bfloat16 hi = __float2bfloat16(v);
    *dst = (seg == 1) ? __float2bfloat16(v - __bfloat162float(hi)) : hi;
}

// ---------------- x conversion: (B,C,N) fp32 -> (B,12,NPIX,64) split bf16 [hi|hi|lo] ----------------
__global__ __launch_bounds__(256) void convert_x_kernel(const float* __restrict__ x,
                                                        __nv_bfloat16* __restrict__ dst)
{
    __shared__ float tile[64][65];
    const int b = blockIdx.z, m0 = blockIdx.x * 64, c0 = blockIdx.y * 64;
    const int t = threadIdx.x, tx = t & 63, ty = t >> 6;
    const float* src = x + (size_t)b * CDIM * NPIX;
#pragma unroll
    for (int i = 0; i < 16; i++) {
        int cl = ty + i*4;
        tile[cl][tx] = src[(size_t)(c0 + cl) * NPIX + m0 + tx];
    }
    __syncthreads();
    const int chbase = c0 >> 6;
    const size_t per = (size_t)NPIX * 64;
    const size_t base = (size_t)b * 12 * per;
#pragma unroll
    for (int i = 0; i < 16; i++) {
        int ml = ty + i*4, cl = tx;
        float v = tile[cl][ml];
        __nv_bfloat16 hi = __float2bfloat16(v);
        __nv_bfloat16 lo = __float2bfloat16(v - __bfloat162float(hi));
        size_t row = (size_t)(m0 + ml) * 64 + cl;
        dst[base + (size_t)(chbase    ) * per + row] = hi;
        dst[base + (size_t)(4 + chbase) * per + row] = hi;
        dst[base + (size_t)(8 + chbase) * per + row] = lo;
    }
}

// ---------------- HMMA GEMM: D[m][n] = sum_k A[m][k] * BT[n][k] ----------------
// CTA tile 128 x NTILE, 8 warps (4 along M x 2 along N), warp tile 32 x NTILE/2.
// K consumed in 64-col chunks; tile base for row r, chunk ch = ptr + (m0+r)*RS + ch*CS.
// BIASMODE: 0 = none, 1 = bias[n], 2 = bias[m].
template<int NTILE, int BIASMODE>
__global__ __launch_bounds__(256) void hgemm_kernel(
    const __nv_bfloat16* __restrict__ A, const __nv_bfloat16* __restrict__ BT,
    const float* __restrict__ bias, float* __restrict__ C,
    int nchunks, long aRS, long aCS, long bRS, long bCS,
    size_t A_bstride, size_t B_bstride, size_t C_bstride, int ldc)
{
    constexpr int NFRAG = NTILE / 16;   // n-frags (of 8) per warp
    constexpr int LDS32 = 36;           // smem row pitch in uint32 (64 bf16 + 8 pad)
    __shared__ __align__(16) uint32_t As[128 * LDS32];
    __shared__ __align__(16) uint32_t Bs[NTILE * LDS32];

    const int tid = threadIdx.x, lane = tid & 31, w = tid >> 5;
    const int g = lane >> 2, tig = lane & 3;
    const int wm = (w >> 1) * 32, wn = (w & 1) * (NTILE / 2);
    const int b = blockIdx.z;
    const int m0 = blockIdx.x * 128, n0 = blockIdx.y * NTILE;
    A  += (size_t)b * A_bstride;
    BT += (size_t)b * B_bstride;
    C  += (size_t)b * C_bstride;

    float acc[2][NFRAG][4];
#pragma unroll
    for (int mf = 0; mf < 2; mf++)
#pragma unroll
        for (int nf = 0; nf < NFRAG; nf++)
#pragma unroll
            for (int i = 0; i < 4; i++) acc[mf][nf][i] = 0.f;

    for (int ch = 0; ch < nchunks; ch++) {
        const __nv_bfloat16* Ab = A + (size_t)m0 * aRS + (size_t)ch * aCS;
#pragma unroll
        for (int i = 0; i < 4; i++) {           // 128 rows x 8 uint4
            int e = tid + i * 256;
            int r = e >> 3, s = e & 7;
            uint4 val = *(const uint4*)(Ab + (size_t)r * aRS + s * 8);
            *(uint4*)((char*)As + r * (LDS32 * 4) + s * 16) = val;
        }
        const __nv_bfloat16* Bb = BT + (size_t)n0 * bRS + (size_t)ch * bCS;
#pragma unroll
        for (int i = 0; i < NTILE / 32; i++) {  // NTILE rows x 8 uint4
            int e = tid + i * 256;
            int r = e >> 3, s = e & 7;
            uint4 val = *(const uint4*)(Bb + (size_t)r * bRS + s * 8);
            *(uint4*)((char*)Bs + r * (LDS32 * 4) + s * 16) = val;
        }
        __syncthreads();
#pragma unroll
        for (int ks = 0; ks < 4; ks++) {        // 4 x k16 per 64-chunk
            uint32_t a[2][4], bb[NFRAG][2];
#pragma unroll
            for (int mf = 0; mf < 2; mf++) {
                int r0 = wm + mf * 16;
                a[mf][0] = As[(r0 + g    ) * LDS32 + ks * 8 + tig];
                a[mf][1] = As[(r0 + g + 8) * LDS32 + ks * 8 + tig];
                a[mf][2] = As[(r0 + g    ) * LDS32 + ks * 8 + tig + 4];
                a[mf][3] = As[(r0 + g + 8) * LDS32 + ks * 8 + tig + 4];
            }
#pragma unroll
            for (int nf = 0; nf < NFRAG; nf++) {
                int rn = wn + nf * 8 + g;
                bb[nf][0] = Bs[rn * LDS32 + ks * 8 + tig];
                bb[nf][1] = Bs[rn * LDS32 + ks * 8 + tig + 4];
            }
#pragma unroll
            for (int mf = 0; mf < 2; mf++)
#pragma unroll
                for (int nf = 0; nf < NFRAG; nf++)
                    mma_bf16(acc[mf][nf], a[mf], bb[nf]);
        }
        __syncthreads();
    }

    // epilogue: d0,d1 -> row m cols n,n+1 ; d2,d3 -> row m+8
#pragma unroll
    for (int mf = 0; mf < 2; mf++) {
        int m = m0 + wm + mf * 16 + g;
#pragma unroll
        for (int nf = 0; nf < NFRAG; nf++) {
            int n = n0 + wn + nf * 8 + 2 * tig;
            float b0 = 0.f, b1 = 0.f, b2 = 0.f, b3 = 0.f;
            if (BIASMODE == 1) { b0 = bias[n]; b1 = bias[n + 1]; b2 = b0; b3 = b1; }
            if (BIASMODE == 2) { b0 = b1 = bias[m]; b2 = b3 = bias[m + 8]; }
            *(float2*)(C + (size_t)m * ldc + n) =
                make_float2(acc[mf][nf][0] + b0, acc[mf][nf][1] + b1);
            *(float2*)(C + (size_t)(m + 8) * ldc + n) =
                make_float2(acc[mf][nf][2] + b2, acc[mf][nf][3] + b3);
        }
    }
}

// ---------------- fused softmax + bilinear sampling -> split-bf16 catS ----------------
__global__ __launch_bounds__(256) void sample_kernel()
{
    const int n = blockIdx.x;
    const int b = blockIdx.y;
    const int q = blockIdx.z;
    const int tid = threadIdx.x;
    const int h = tid >> 5;
    const int j = tid & 31;

    const float* __restrict__ owp =
        g_ow + ((size_t)q * NB * NPIX + (size_t)b * NPIX + n) * OWCOLS;

    float logit = owp[2 * HP + j];
    float mx = logit;
#pragma unroll
    for (int o = 16; o; o >>= 1) mx = fmaxf(mx, __shfl_xor_sync(0xffffffffu, mx, o));
    float ex = __expf(logit - mx);
    float sm = ex;
#pragma unroll
    for (int o = 16; o; o >>= 1) sm += __shfl_xor_sync(0xffffffffu, sm, o);
    float aw = ex / sm;

    const int px = n & (HWDIM - 1);
    const int py = n >> 7;
    const float refx = ((float)px + 0.5f) / (float)HWDIM;
    const float refy = ((float)py + 0.5f) / (float)HWDIM;

    const float* __restrict__ vb = g_v + (size_t)b * NPIX * CDIM + h * 32 + j;
    const float2* __restrict__ offp = (const float2*)(owp + h * (2 * NPTS));
    float acc = 0.f;
#pragma unroll
    for (int p = 0; p < NPTS; p++) {
        float ax = __shfl_sync(0xffffffffu, aw, h * NPTS + p);
        float2 o2 = offp[p];
        float gx = 2.0f * (refx + o2.x) - 1.0f;
        float gy = 2.0f * (refy + o2.y) - 1.0f;
        float ix = ((gx + 1.0f) * (float)HWDIM - 1.0f) * 0.5f;
        float iy = ((gy + 1.0f) * (float)HWDIM - 1.0f) * 0.5f;
        float x0f = floorf(ix), y0f = floorf(iy);
        float wx1 = ix - x0f,   wy1 = iy - y0f;
        int x0 = (int)x0f, y0 = (int)y0f;
        float w00 = (1.f - wx1) * (1.f - wy1);
        float w10 = wx1 * (1.f - wy1);
        float w01 = (1.f - wx1) * wy1;
        float w11 = wx1 * wy1;
        float s = 0.f;
        if ((unsigned)x0 < HWDIM && (unsigned)y0 < HWDIM)
            s = fmaf(w00, vb[(size_t)(y0 * HWDIM + x0) * CDIM], s);
        if ((unsigned)(x0 + 1) < HWDIM && (unsigned)y0 < HWDIM)
            s = fmaf(w10, vb[(size_t)(y0 * HWDIM + x0 + 1) * CDIM], s);
        if ((unsigned)x0 < HWDIM && (unsigned)(y0 + 1) < HWDIM)
            s = fmaf(w01, vb[(size_t)((y0 + 1) * HWDIM + x0) * CDIM], s);
        if ((unsigned)(x0 + 1) < HWDIM && (unsigned)(y0 + 1) < HWDIM)
            s = fmaf(w11, vb[(size_t)((y0 + 1) * HWDIM + x0 + 1) * CDIM], s);
        acc = fmaf(ax, s, acc);
    }
    // split-bf16 cat operand: chunks [hi(0-7) | hi(8-15) | lo(16-23)]
    __nv_bfloat16 hi = __float2bfloat16(acc);
    __nv_bfloat16 lo = __float2bfloat16(acc - __bfloat162float(hi));
    const int qc = q * CDIM + h * 32 + j;
    const size_t per = (size_t)NPIX * 64;
    const size_t base = (size_t)b * 24 * per + (size_t)n * 64 + (qc & 63);
    const int ch = qc >> 6;
    g_catS[base + (size_t)(ch     ) * per] = hi;
    g_catS[base + (size_t)(8 + ch ) * per] = hi;
    g_catS[base + (size_t)(16 + ch) * per] = lo;
}

// ---------------- launch ----------------
extern "C" void kernel_launch(void* const* d_in, const int* in_sizes, int n_in,
                              void* d_out, int out_size)
{
    const float* x1    = (const float*)d_in[0];
    const float* x2    = (const float*)d_in[1];
    const float* x3    = (const float*)d_in[2];
    const float* Wv    = (const float*)d_in[3];
    const float* Woff1 = (const float*)d_in[4];
    const float* boff1 = (const float*)d_in[5];
    const float* Woff2 = (const float*)d_in[6];
    const float* boff2 = (const float*)d_in[7];
    const float* Waw1  = (const float*)d_in[8];
    const float* baw1  = (const float*)d_in[9];
    const float* Waw2  = (const float*)d_in[10];
    const float* baw2  = (const float*)d_in[11];
    const float* Wout  = (const float*)d_in[12];
    const float* bout  = (const float*)d_in[13];
    float* out = (float*)d_out;

    __nv_bfloat16 *p_x1S, *p_x2S, *p_x3S, *p_catS, *p_WTv, *p_WTow, *p_WTout;
    float *p_v, *p_ow, *p_b96;
    cudaGetSymbolAddress((void**)&p_x1S,  g_x1S);
    cudaGetSymbolAddress((void**)&p_x2S,  g_x2S);
    cudaGetSymbolAddress((void**)&p_x3S,  g_x3S);
    cudaGetSymbolAddress((void**)&p_catS, g_catS);
    cudaGetSymbolAddress((void**)&p_WTv,  g_WTv);
    cudaGetSymbolAddress((void**)&p_WTow, g_WTow);
    cudaGetSymbolAddress((void**)&p_WTout,g_WTout);
    cudaGetSymbolAddress((void**)&p_v,    g_v);
    cudaGetSymbolAddress((void**)&p_ow,   g_ow);
    cudaGetSymbolAddress((void**)&p_b96,  g_b96);

    // 1) weight transpose + split
    const int WTOT = 256*768 + 2*96*768 + 256*1536 + 2*OWCOLS;
    convert_w_kernel<<<(WTOT + 255) / 256, 256>>>(
        Wv, Woff1, Waw1, Woff2, Waw2, boff1, baw1, boff2, baw2, Wout);

    // 2) x transpose + split
    dim3 cg(NPIX / 64, CDIM / 64, NB);
    convert_x_kernel<<<cg, 256>>>(x1, p_x1S);
    convert_x_kernel<<<cg, 256>>>(x2, p_x2S);
    convert_x_kernel<<<cg, 256>>>(x3, p_x3S);

    // 3) v = x3 @ Wv -> g_v (b, pix, c)
    hgemm_kernel<128, 0><<<dim3(NPIX/128, CDIM/128, NB), 256>>>(
        p_x3S, p_WTv, nullptr, p_v,
        12, /*aRS=*/64, /*aCS=*/(long)NPIX*64, /*bRS=*/768, /*bCS=*/64,
        (size_t)12*NPIX*64, 0, (size_t)NPIX*CDIM, CDIM);

    // 4) [off|aw] = x{1,2} @ W96 + b96 -> g_ow
    hgemm_kernel<96, 1><<<dim3(NPIX/128, 1, NB), 256>>>(
        p_x1S, p_WTow, p_b96, p_ow,
        12, 64, (long)NPIX*64, 768, 64,
        (size_t)12*NPIX*64, 0, (size_t)NPIX*OWCOLS, OWCOLS);
    hgemm_kernel<96, 1><<<dim3(NPIX/128, 1, NB), 256>>>(
        p_x2S, p_WTow + 96*768, p_b96 + OWCOLS, p_ow + (size_t)NB*NPIX*OWCOLS,
        12, 64, (long)NPIX*64, 768, 64,
        (size_t)12*NPIX*64, 0, (size_t)NPIX*OWCOLS, OWCOLS);

    // 5) softmax + bilinear sample -> split-bf16 catS
    sample_kernel<<<dim3(NPIX, NB, 2), 256>>>();

    // 6) out^T: D[c][pix] = Wout_T @ cat_T  + bout  -> direct (B,C,H,W) layout
    hgemm_kernel<128, 2><<<dim3(CDIM/128, NPIX/128, NB), 256>>>(
        p_WTout, p_catS, bout, out,
        24, /*aRS=*/1536, /*aCS=*/64, /*bRS=*/64, /*bCS=*/(long)NPIX*64,
        0, (size_t)24*NPIX*64, (size_t)CDIM*NPIX, NPIX);
}